// round 16
// baseline (speedup 1.0000x reference)
#include <cuda_runtime.h>
#include <cuda_fp16.h>
#include <cstdint>

#define Bsz 2048
#define Dsz 512
#define Hsz 1024
#define Ssz 100
#define KTOP 51

// Scratch (device globals — no allocations allowed)
__device__ float g_epsmean[Bsz * Dsz];   // mean over S of eps, 4 MB
__device__ float2 g_ms[Bsz * Dsz];       // interleaved (mu, std), 8 MB

// Pre-split fp16 hi/lo operand arrays (fp16x3 compensated GEMM)
__device__ __align__(16) __half g_bA_hi[Bsz * Dsz];   // batch
__device__ __align__(16) __half g_bA_lo[Bsz * Dsz];
__device__ __align__(16) __half g_w1_hi[Hsz * Dsz];   // W1
__device__ __align__(16) __half g_w1_lo[Hsz * Dsz];
__device__ __align__(16) __half g_hA_hi[Bsz * Hsz];   // relu(fc1) split
__device__ __align__(16) __half g_hA_lo[Bsz * Hsz];
__device__ __align__(16) __half g_w2_hi[Hsz * Hsz];   // [W21;W22] interleaved blocks
__device__ __align__(16) __half g_w2_lo[Hsz * Hsz];

// ---------------------------------------------------------------------------
// Helpers
// ---------------------------------------------------------------------------
__device__ __forceinline__ uint32_t smem_u32(const void* p) {
    uint32_t a;
    asm("{ .reg .u64 t; cvta.to.shared.u64 t, %1; cvt.u32.u64 %0, t; }" : "=r"(a) : "l"(p));
    return a;
}

#define CP16(dst, src) \
    asm volatile("cp.async.cg.shared.global [%0], [%1], 16;" :: "r"(dst), "l"(src))
#define CP_COMMIT() asm volatile("cp.async.commit_group;" ::: "memory")
#define CP_WAIT2()  asm volatile("cp.async.wait_group 2;" ::: "memory")
#define CP_WAIT1()  asm volatile("cp.async.wait_group 1;" ::: "memory")
#define CP_WAIT0()  asm volatile("cp.async.wait_group 0;" ::: "memory")

// fp16x3 split of a float pair into packed hi + residual-lo half2.
__device__ __forceinline__ void split_h2(float x0, float x1, uint32_t& hi, uint32_t& lo) {
    __half2 h = __floats2half2_rn(x0, x1);
    hi = *(uint32_t*)&h;
    float2 f = __half22float2(h);
    __half2 l = __floats2half2_rn(x0 - f.x, x1 - f.y);
    lo = *(uint32_t*)&l;
}

__device__ __forceinline__ void mma16(float* d, const uint32_t* a, const uint32_t* b) {
    asm volatile(
        "mma.sync.aligned.m16n8k16.row.col.f32.f16.f16.f32 "
        "{%0,%1,%2,%3}, {%4,%5,%6,%7}, {%8,%9}, {%0,%1,%2,%3};\n"
        : "+f"(d[0]), "+f"(d[1]), "+f"(d[2]), "+f"(d[3])
        : "r"(a[0]), "r"(a[1]), "r"(a[2]), "r"(a[3]), "r"(b[0]), "r"(b[1]));
}

// smem half-tile geometry: 128 rows x 32 halves, LDH=40 halves (80 B) pitch.
#define LDH 40
#define TILE_B (128 * LDH * 2)   // 10240 B
#define BUF_B  (4 * TILE_B)      // A_hi, A_lo, B_hi, B_lo = 40960 B
#define SMEM_TOT (3 * BUF_B)     // 3-stage pipeline = 122880 B

// ---------------------------------------------------------------------------
// Kernel 0: merged operand prep.  Flat float4-index ranges:
//   [0, 262144)      : split batch  (2048*512/4)
//   [262144, 393216) : split W1     (1024*512/4)
//   [393216, 655360) : combined-layout split of [W21;W22]  (1024*1024/4)
// ---------------------------------------------------------------------------
#define PREP_BA 262144
#define PREP_W1 (PREP_BA + 131072)            // 393216
#define PREP_TOT (PREP_W1 + 262144)           // 655360

__global__ void k_prep(const float4* __restrict__ batch, const float4* __restrict__ W1,
                       const float4* __restrict__ W21, const float4* __restrict__ W22) {
    int i = blockIdx.x * blockDim.x + threadIdx.x;
    uint32_t h0, l0, h1, l1;
    if (i < PREP_BA) {
        float4 v = __ldg(batch + i);
        split_h2(v.x, v.y, h0, l0);
        split_h2(v.z, v.w, h1, l1);
        ((uint2*)g_bA_hi)[i] = make_uint2(h0, h1);
        ((uint2*)g_bA_lo)[i] = make_uint2(l0, l1);
    } else if (i < PREP_W1) {
        int j = i - PREP_BA;
        float4 v = __ldg(W1 + j);
        split_h2(v.x, v.y, h0, l0);
        split_h2(v.z, v.w, h1, l1);
        ((uint2*)g_w1_hi)[j] = make_uint2(h0, h1);
        ((uint2*)g_w1_lo)[j] = make_uint2(l0, l1);
    } else {
        int j = i - PREP_W1;                 // float4 index into combined W2
        int n = j >> 8, kq = j & 255;        // 256 float4 per 1024-col row
        int blk = n >> 7, r = n & 127;
        const float4* src = (r < 64) ? (W21 + (size_t)(blk * 64 + r) * 256 + kq)
                                     : (W22 + (size_t)(blk * 64 + r - 64) * 256 + kq);
        float4 v = __ldg(src);
        split_h2(v.x, v.y, h0, l0);
        split_h2(v.z, v.w, h1, l1);
        ((uint2*)g_w2_hi)[j] = make_uint2(h0, h1);
        ((uint2*)g_w2_lo)[j] = make_uint2(l0, l1);
    }
}

// ---------------------------------------------------------------------------
// Kernel 1: eps_mean = mean_s eps[s].  Grid 128 x 256 thr (low occupancy,
// high MLP=8) so it CO-RESIDES with the GEMM CTAs on a side stream and
// streams HBM while the GEMMs crunch HMMA.
// ---------------------------------------------------------------------------
__global__ void __launch_bounds__(256, 1) k_epsmean(const float4* __restrict__ eps4) {
    const int nd4 = Bsz * Dsz / 4;                // 262144
    const int base = blockIdx.x * 2048 + threadIdx.x;
    float4 acc[8];
#pragma unroll
    for (int j = 0; j < 8; j++) acc[j] = make_float4(0.f, 0.f, 0.f, 0.f);
#pragma unroll 1
    for (int s = 0; s < Ssz; s++) {
        const float4* sp = eps4 + (size_t)s * nd4 + base;
        float4 x[8];
#pragma unroll
        for (int j = 0; j < 8; j++) x[j] = __ldg(sp + j * 256);
#pragma unroll
        for (int j = 0; j < 8; j++) {
            acc[j].x += x[j].x; acc[j].y += x[j].y;
            acc[j].z += x[j].z; acc[j].w += x[j].w;
        }
    }
    const float inv = 1.0f / (float)Ssz;
    float4* dst = ((float4*)g_epsmean) + base;
#pragma unroll
    for (int j = 0; j < 8; j++) {
        float4 r = make_float4(acc[j].x * inv, acc[j].y * inv,
                               acc[j].z * inv, acc[j].w * inv);
        dst[j * 256] = r;
    }
}

// ---------------------------------------------------------------------------
// Fragment-load helper: uint32 (= half2) at (row, kc) of a half tile.
// ---------------------------------------------------------------------------
__device__ __forceinline__ uint32_t ldfrag(const uint32_t* t, int r, int kc) {
    return t[r * (LDH / 2) + (kc >> 1)];
}

// ---------------------------------------------------------------------------
// Kernel 2: h = relu(batch @ W1^T + b1), pure HMMA mainloop on pre-split
// operands; 3-stage cp.async pipeline.  Epilogue writes h in split hi/lo
// form for gemm2.  128x128 CTA tile, BK=32, 256 threads.
// ---------------------------------------------------------------------------
__global__ void __launch_bounds__(256, 1)
k_gemm1(const float* __restrict__ bias) {
    extern __shared__ __align__(16) char sm[];
    const uint32_t sbase = smem_u32(sm);
    const int tid = threadIdx.x, lane = tid & 31, wid = tid >> 5;
    const int warpM = wid >> 2, warpN = wid & 3;
    const int grp = lane >> 2, tig = lane & 3;
    const int rowBase = blockIdx.y * 128, colBase = blockIdx.x * 128;

    float acc[4][4][4];
#pragma unroll
    for (int mi = 0; mi < 4; mi++)
#pragma unroll
        for (int ni = 0; ni < 4; ni++)
#pragma unroll
            for (int j = 0; j < 4; j++) acc[mi][ni][j] = 0.f;

#define G1_LOAD(c, q)                                                               \
    do {                                                                            \
        int k0 = (c) * 32;                                                          \
        uint32_t sb0 = sbase + (q) * BUF_B;                                         \
        _Pragma("unroll")                                                           \
        for (int it = 0; it < 2; it++) {                                            \
            int f = tid + it * 256;                                                 \
            int r = f >> 2, c8 = f & 3;                                             \
            uint32_t dst = sb0 + (r * LDH + c8 * 8) * 2;                            \
            size_t ao = (size_t)(rowBase + r) * Dsz + k0 + c8 * 8;                  \
            size_t bo = (size_t)(colBase + r) * Dsz + k0 + c8 * 8;                  \
            CP16(dst,              (const char*)g_bA_hi + ao * 2);                  \
            CP16(dst + TILE_B,     (const char*)g_bA_lo + ao * 2);                  \
            CP16(dst + 2 * TILE_B, (const char*)g_w1_hi + bo * 2);                  \
            CP16(dst + 3 * TILE_B, (const char*)g_w1_lo + bo * 2);                  \
        }                                                                           \
        CP_COMMIT();                                                                \
    } while (0)

    G1_LOAD(0, 0);
    G1_LOAD(1, 1);
    for (int c = 0; c < 16; c++) {
        const int q = c % 3;
        if (c + 2 < 16) { G1_LOAD(c + 2, (c + 2) % 3); CP_WAIT2(); }
        else if (c + 1 < 16) { CP_WAIT1(); }
        else { CP_WAIT0(); }
        __syncthreads();
        const uint32_t* ah_t = (const uint32_t*)(sm + q * BUF_B);
        const uint32_t* al_t = (const uint32_t*)(sm + q * BUF_B + TILE_B);
        const uint32_t* bh_t = (const uint32_t*)(sm + q * BUF_B + 2 * TILE_B);
        const uint32_t* bl_t = (const uint32_t*)(sm + q * BUF_B + 3 * TILE_B);
#pragma unroll
        for (int kk = 0; kk < 2; kk++) {
            const int kc = kk * 16 + tig * 2;
            uint32_t ah[4][4], al[4][4], bh[4][2], bl[4][2];
#pragma unroll
            for (int mi = 0; mi < 4; mi++) {
                int r = warpM * 64 + mi * 16 + grp;
                ah[mi][0] = ldfrag(ah_t, r, kc);     al[mi][0] = ldfrag(al_t, r, kc);
                ah[mi][1] = ldfrag(ah_t, r + 8, kc); al[mi][1] = ldfrag(al_t, r + 8, kc);
                ah[mi][2] = ldfrag(ah_t, r, kc + 8); al[mi][2] = ldfrag(al_t, r, kc + 8);
                ah[mi][3] = ldfrag(ah_t, r + 8, kc + 8); al[mi][3] = ldfrag(al_t, r + 8, kc + 8);
            }
#pragma unroll
            for (int ni = 0; ni < 4; ni++) {
                int n = warpN * 32 + ni * 8 + grp;
                bh[ni][0] = ldfrag(bh_t, n, kc);     bl[ni][0] = ldfrag(bl_t, n, kc);
                bh[ni][1] = ldfrag(bh_t, n, kc + 8); bl[ni][1] = ldfrag(bl_t, n, kc + 8);
            }
#pragma unroll
            for (int mi = 0; mi < 4; mi++)
#pragma unroll
                for (int ni = 0; ni < 4; ni++) {
                    mma16(acc[mi][ni], ah[mi], bh[ni]);
                    mma16(acc[mi][ni], ah[mi], bl[ni]);
                    mma16(acc[mi][ni], al[mi], bh[ni]);
                }
        }
        __syncthreads();
    }
#undef G1_LOAD

#pragma unroll
    for (int mi = 0; mi < 4; mi++) {
        int r0 = rowBase + warpM * 64 + mi * 16 + grp;
#pragma unroll
        for (int ni = 0; ni < 4; ni++) {
            int c = colBase + warpN * 32 + ni * 8 + tig * 2;
            float b0 = __ldg(bias + c), b1 = __ldg(bias + c + 1);
            float v00 = fmaxf(acc[mi][ni][0] + b0, 0.f);
            float v01 = fmaxf(acc[mi][ni][1] + b1, 0.f);
            float v10 = fmaxf(acc[mi][ni][2] + b0, 0.f);
            float v11 = fmaxf(acc[mi][ni][3] + b1, 0.f);
            uint32_t h, l;
            split_h2(v00, v01, h, l);
            *(uint32_t*)(g_hA_hi + (size_t)r0 * Hsz + c) = h;
            *(uint32_t*)(g_hA_lo + (size_t)r0 * Hsz + c) = l;
            split_h2(v10, v11, h, l);
            *(uint32_t*)(g_hA_hi + (size_t)(r0 + 8) * Hsz + c) = h;
            *(uint32_t*)(g_hA_lo + (size_t)(r0 + 8) * Hsz + c) = l;
        }
    }
}

// ---------------------------------------------------------------------------
// Kernel 3: fused dual GEMM on pre-split h and combined W2; 3-stage
// cp.async pipeline.  128(M)x128(N) tile over K=1024; D cols 0-63 = mu,
// 64-127 = log_var.  Epilogue writes interleaved (mu+b21, exp(0.5*(lv+b22)))
// pairs to g_ms; eps_mean + mask are applied later in k_topk (so this
// kernel has NO dependency on the overlapped eps reduction).
// ---------------------------------------------------------------------------
__global__ void __launch_bounds__(256, 1)
k_gemm2(const float* __restrict__ b21, const float* __restrict__ b22) {
    extern __shared__ __align__(16) char sm[];
    const uint32_t sbase = smem_u32(sm);
    const int tid = threadIdx.x, lane = tid & 31, wid = tid >> 5;
    const int warpM = wid >> 2, warpN = wid & 3;
    const int grp = lane >> 2, tig = lane & 3;
    const int rowBase = blockIdx.y * 128, colBase = blockIdx.x * 64;
    const int w2Base = blockIdx.x * 128;   // combined-layout row block

    float acc[4][4][4];
#pragma unroll
    for (int mi = 0; mi < 4; mi++)
#pragma unroll
        for (int ni = 0; ni < 4; ni++)
#pragma unroll
            for (int j = 0; j < 4; j++) acc[mi][ni][j] = 0.f;

#define G2_LOAD(c, q)                                                               \
    do {                                                                            \
        int k0 = (c) * 32;                                                          \
        uint32_t sb0 = sbase + (q) * BUF_B;                                         \
        _Pragma("unroll")                                                           \
        for (int it = 0; it < 2; it++) {                                            \
            int f = tid + it * 256;                                                 \
            int r = f >> 2, c8 = f & 3;                                             \
            uint32_t dst = sb0 + (r * LDH + c8 * 8) * 2;                            \
            size_t ao = (size_t)(rowBase + r) * Hsz + k0 + c8 * 8;                  \
            size_t bo = (size_t)(w2Base + r) * Hsz + k0 + c8 * 8;                   \
            CP16(dst,              (const char*)g_hA_hi + ao * 2);                  \
            CP16(dst + TILE_B,     (const char*)g_hA_lo + ao * 2);                  \
            CP16(dst + 2 * TILE_B, (const char*)g_w2_hi + bo * 2);                  \
            CP16(dst + 3 * TILE_B, (const char*)g_w2_lo + bo * 2);                  \
        }                                                                           \
        CP_COMMIT();                                                                \
    } while (0)

    G2_LOAD(0, 0);
    G2_LOAD(1, 1);
    for (int c = 0; c < 32; c++) {
        const int q = c % 3;
        if (c + 2 < 32) { G2_LOAD(c + 2, (c + 2) % 3); CP_WAIT2(); }
        else if (c + 1 < 32) { CP_WAIT1(); }
        else { CP_WAIT0(); }
        __syncthreads();
        const uint32_t* ah_t = (const uint32_t*)(sm + q * BUF_B);
        const uint32_t* al_t = (const uint32_t*)(sm + q * BUF_B + TILE_B);
        const uint32_t* bh_t = (const uint32_t*)(sm + q * BUF_B + 2 * TILE_B);
        const uint32_t* bl_t = (const uint32_t*)(sm + q * BUF_B + 3 * TILE_B);
#pragma unroll
        for (int kk = 0; kk < 2; kk++) {
            const int kc = kk * 16 + tig * 2;
            uint32_t ah[4][4], al[4][4], bh[4][2], bl[4][2];
#pragma unroll
            for (int mi = 0; mi < 4; mi++) {
                int r = warpM * 64 + mi * 16 + grp;
                ah[mi][0] = ldfrag(ah_t, r, kc);     al[mi][0] = ldfrag(al_t, r, kc);
                ah[mi][1] = ldfrag(ah_t, r + 8, kc); al[mi][1] = ldfrag(al_t, r + 8, kc);
                ah[mi][2] = ldfrag(ah_t, r, kc + 8); al[mi][2] = ldfrag(al_t, r, kc + 8);
                ah[mi][3] = ldfrag(ah_t, r + 8, kc + 8); al[mi][3] = ldfrag(al_t, r + 8, kc + 8);
            }
#pragma unroll
            for (int ni = 0; ni < 4; ni++) {
                int n = warpN * 32 + ni * 8 + grp;
                bh[ni][0] = ldfrag(bh_t, n, kc);     bl[ni][0] = ldfrag(bl_t, n, kc);
                bh[ni][1] = ldfrag(bh_t, n, kc + 8); bl[ni][1] = ldfrag(bl_t, n, kc + 8);
            }
#pragma unroll
            for (int mi = 0; mi < 4; mi++)
#pragma unroll
                for (int ni = 0; ni < 4; ni++) {
                    mma16(acc[mi][ni], ah[mi], bh[ni]);
                    mma16(acc[mi][ni], ah[mi], bl[ni]);
                    mma16(acc[mi][ni], al[mi], bh[ni]);
                }
        }
        __syncthreads();
    }
#undef G2_LOAD

    // Stage D (128 x 128) into smem to pair mu (cols 0-63) with lv (64-127).
    float* Dsm = (float*)sm;  // 128*132*4 = 67584 B <= 122880 B
#pragma unroll
    for (int mi = 0; mi < 4; mi++) {
        int r = warpM * 64 + mi * 16 + grp;
#pragma unroll
        for (int ni = 0; ni < 4; ni++) {
            int n = warpN * 32 + ni * 8 + tig * 2;
            *(float2*)&Dsm[r * 132 + n] = make_float2(acc[mi][ni][0], acc[mi][ni][1]);
            *(float2*)&Dsm[(r + 8) * 132 + n] = make_float2(acc[mi][ni][2], acc[mi][ni][3]);
        }
    }
    __syncthreads();

#pragma unroll
    for (int it = 0; it < 16; it++) {
        int f = tid + it * 256;       // 4096 = 128 rows x 32 col-pairs
        int r = f >> 5, c2 = f & 31;
        int gr = rowBase + r, gc = colBase + c2 * 2;
        float mu0 = Dsm[r * 132 + c2 * 2]     + __ldg(b21 + gc);
        float mu1 = Dsm[r * 132 + c2 * 2 + 1] + __ldg(b21 + gc + 1);
        float lv0 = Dsm[r * 132 + 64 + c2 * 2]     + __ldg(b22 + gc);
        float lv1 = Dsm[r * 132 + 64 + c2 * 2 + 1] + __ldg(b22 + gc + 1);
        float4 v = make_float4(mu0, expf(0.5f * lv0), mu1, expf(0.5f * lv1));
        *(float4*)(g_ms + (size_t)gr * Dsz + gc) = v;
    }
}

// ---------------------------------------------------------------------------
// Kernel 4: compute op = (batch!=0)*(mu + eps_mean*std) on the fly, then
// stable top-51 of 512 per row.  One warp per TWO rows (ILP), radix-select
// with both counts packed into one __reduce_add_sync.
// ---------------------------------------------------------------------------
__global__ void k_topk(const float* __restrict__ batch, float* __restrict__ out) {
    const int warp = threadIdx.x >> 5;
    const int lane = threadIdx.x & 31;
    const int row0 = blockIdx.x * 16 + warp * 2;

    float v[2][16];
    unsigned u[2][16];
#pragma unroll
    for (int rr = 0; rr < 2; rr++) {
        const float2* ms = g_ms + (size_t)(row0 + rr) * Dsz;
        const float* em = g_epsmean + (size_t)(row0 + rr) * Dsz;
        const float* bt = batch + (size_t)(row0 + rr) * Dsz;
#pragma unroll
        for (int i = 0; i < 16; i++) {
            int c = lane + 32 * i;
            float2 p = __ldg(ms + c);
            float e = __ldg(em + c);
            float m = __ldg(bt + c);
            float val = (m != 0.f) ? fmaf(e, p.y, p.x) : 0.f;
            v[rr][i] = val;
            unsigned b = __float_as_uint(val);
            u[rr][i] = (b & 0x80000000u) ? ~b : (b | 0x80000000u);
        }
    }

    unsigned T0 = 0u, T1 = 0u;
#pragma unroll 1
    for (int bit = 31; bit >= 0; --bit) {
        unsigned cand0 = T0 | (1u << bit);
        unsigned cand1 = T1 | (1u << bit);
        int c0 = 0, c1 = 0;
#pragma unroll
        for (int i = 0; i < 16; i++) {
            c0 += (u[0][i] >= cand0) ? 1 : 0;
            c1 += (u[1][i] >= cand1) ? 1 : 0;
        }
        unsigned s = __reduce_add_sync(0xffffffffu, (unsigned)(c0 | (c1 << 16)));
        if ((s & 0xffffu) >= KTOP) T0 = cand0;
        if ((s >> 16) >= KTOP) T1 = cand1;
    }

    unsigned T[2] = {T0, T1};
#pragma unroll
    for (int rr = 0; rr < 2; rr++) {
        int g = 0;
#pragma unroll
        for (int i = 0; i < 16; i++) g += (u[rr][i] > T[rr]) ? 1 : 0;
        g = (int)__reduce_add_sync(0xffffffffu, (unsigned)g);

        float* dst = out + (size_t)(row0 + rr) * Dsz;
        int pre = g;
#pragma unroll
        for (int i = 0; i < 16; i++) {
            unsigned bal = __ballot_sync(0xffffffffu, u[rr][i] == T[rr]);
            int before = pre + __popc(bal & ((1u << lane) - 1u));
            bool keep = (u[rr][i] > T[rr]) || ((u[rr][i] == T[rr]) && (before < KTOP));
            dst[lane + 32 * i] = keep ? v[rr][i] : 0.f;
            pre += __popc(bal);
        }
    }
}

// ---------------------------------------------------------------------------
extern "C" void kernel_launch(void* const* d_in, const int* in_sizes, int n_in,
                              void* d_out, int out_size) {
    const float* batch = (const float*)d_in[0];
    const float* W1    = (const float*)d_in[1];
    const float* b1    = (const float*)d_in[2];
    const float* W21   = (const float*)d_in[3];
    const float* b21   = (const float*)d_in[4];
    const float* W22   = (const float*)d_in[5];
    const float* b22   = (const float*)d_in[6];
    const float* eps   = (const float*)d_in[7];
    float* out = (float*)d_out;

    static cudaStream_t s2 = nullptr;
    static cudaEvent_t evFork = nullptr, evEps = nullptr;
    if (s2 == nullptr) {
        cudaStreamCreateWithFlags(&s2, cudaStreamNonBlocking);
        cudaEventCreateWithFlags(&evFork, cudaEventDisableTiming);
        cudaEventCreateWithFlags(&evEps, cudaEventDisableTiming);
        cudaFuncSetAttribute(k_gemm1, cudaFuncAttributeMaxDynamicSharedMemorySize, SMEM_TOT);
        cudaFuncSetAttribute(k_gemm2, cudaFuncAttributeMaxDynamicSharedMemorySize, SMEM_TOT);
    }

    // Merged operand prep (batch, W1, combined W2)
    k_prep<<<PREP_TOT / 256, 256>>>((const float4*)batch, (const float4*)W1,
                                    (const float4*)W21, (const float4*)W22);

    // Fork: small-grid eps reduction co-resides with the GEMM CTAs.
    cudaEventRecord(evFork, 0);
    cudaStreamWaitEvent(s2, evFork, 0);
    k_epsmean<<<128, 256, 0, s2>>>((const float4*)eps);
    cudaEventRecord(evEps, s2);

    k_gemm1<<<dim3(Hsz / 128, Bsz / 128), 256, SMEM_TOT>>>(b1);
    k_gemm2<<<dim3(Dsz / 64, Bsz / 128), 256, SMEM_TOT>>>(b21, b22);

    // Join: topk consumes eps_mean + (mu, std).
    cudaStreamWaitEvent(0, evEps, 0);
    k_topk<<<Bsz / 16, 256>>>(batch, out);
}

// round 17
// speedup vs baseline: 1.4436x; 1.4436x over previous
#include <cuda_runtime.h>
#include <cuda_fp16.h>
#include <cstdint>

#define Bsz 2048
#define Dsz 512
#define Hsz 1024
#define Ssz 100
#define KTOP 51

// Scratch (device globals — no allocations allowed)
__device__ float g_epsmean[Bsz * Dsz];   // mean over S of eps, 4 MB
__device__ float g_op[Bsz * Dsz];        // pre-topk op, 4 MB

// Pre-split fp16 hi/lo operand arrays (fp16x3 compensated GEMM)
__device__ __align__(16) __half g_bA_hi[Bsz * Dsz];   // batch
__device__ __align__(16) __half g_bA_lo[Bsz * Dsz];
__device__ __align__(16) __half g_w1_hi[Hsz * Dsz];   // W1
__device__ __align__(16) __half g_w1_lo[Hsz * Dsz];
__device__ __align__(16) __half g_hA_hi[Bsz * Hsz];   // relu(fc1) split
__device__ __align__(16) __half g_hA_lo[Bsz * Hsz];
__device__ __align__(16) __half g_w2_hi[Hsz * Hsz];   // [W21;W22] interleaved blocks
__device__ __align__(16) __half g_w2_lo[Hsz * Hsz];

// ---------------------------------------------------------------------------
// Helpers
// ---------------------------------------------------------------------------
__device__ __forceinline__ uint32_t smem_u32(const void* p) {
    uint32_t a;
    asm("{ .reg .u64 t; cvta.to.shared.u64 t, %1; cvt.u32.u64 %0, t; }" : "=r"(a) : "l"(p));
    return a;
}

#define CP16(dst, src) \
    asm volatile("cp.async.cg.shared.global [%0], [%1], 16;" :: "r"(dst), "l"(src))
#define CP_COMMIT() asm volatile("cp.async.commit_group;" ::: "memory")
#define CP_WAIT2()  asm volatile("cp.async.wait_group 2;" ::: "memory")
#define CP_WAIT1()  asm volatile("cp.async.wait_group 1;" ::: "memory")
#define CP_WAIT0()  asm volatile("cp.async.wait_group 0;" ::: "memory")

// fp16x3 split of a float pair into packed hi + residual-lo half2.
__device__ __forceinline__ void split_h2(float x0, float x1, uint32_t& hi, uint32_t& lo) {
    __half2 h = __floats2half2_rn(x0, x1);
    hi = *(uint32_t*)&h;
    float2 f = __half22float2(h);
    __half2 l = __floats2half2_rn(x0 - f.x, x1 - f.y);
    lo = *(uint32_t*)&l;
}

__device__ __forceinline__ void mma16(float* d, const uint32_t* a, const uint32_t* b) {
    asm volatile(
        "mma.sync.aligned.m16n8k16.row.col.f32.f16.f16.f32 "
        "{%0,%1,%2,%3}, {%4,%5,%6,%7}, {%8,%9}, {%0,%1,%2,%3};\n"
        : "+f"(d[0]), "+f"(d[1]), "+f"(d[2]), "+f"(d[3])
        : "r"(a[0]), "r"(a[1]), "r"(a[2]), "r"(a[3]), "r"(b[0]), "r"(b[1]));
}

// ldmatrix x4: loads 4 8x8 b16 matrices; lane i supplies the row address of
// matrix (i/8), row (i%8).
__device__ __forceinline__ void ldsm4(uint32_t& r0, uint32_t& r1, uint32_t& r2,
                                      uint32_t& r3, uint32_t addr) {
    asm volatile("ldmatrix.sync.aligned.m8n8.x4.shared.b16 {%0,%1,%2,%3}, [%4];"
                 : "=r"(r0), "=r"(r1), "=r"(r2), "=r"(r3) : "r"(addr));
}

// smem half-tile geometry: 128 rows x 32 halves, LDH=40 halves (80 B) pitch.
// ldmatrix 8-row groups stride 80 B -> bank starts {0,20,8,28,16,4,24,12}:
// all 32 banks covered exactly once per phase, conflict-free.
#define LDH 40
#define TILE_B (128 * LDH * 2)   // 10240 B
#define BUF_B  (4 * TILE_B)      // A_hi, A_lo, B_hi, B_lo = 40960 B
#define SMEM_TOT (3 * BUF_B)     // 3-stage pipeline = 122880 B

// ---------------------------------------------------------------------------
// Kernel 0: merged operand prep.  Flat float4-index ranges:
//   [0, 262144)      : split batch  (2048*512/4)
//   [262144, 393216) : split W1     (1024*512/4)
//   [393216, 655360) : combined-layout split of [W21;W22]  (1024*1024/4)
// ---------------------------------------------------------------------------
#define PREP_BA 262144
#define PREP_W1 (PREP_BA + 131072)            // 393216
#define PREP_TOT (PREP_W1 + 262144)           // 655360

__global__ void k_prep(const float4* __restrict__ batch, const float4* __restrict__ W1,
                       const float4* __restrict__ W21, const float4* __restrict__ W22) {
    int i = blockIdx.x * blockDim.x + threadIdx.x;
    uint32_t h0, l0, h1, l1;
    if (i < PREP_BA) {
        float4 v = __ldg(batch + i);
        split_h2(v.x, v.y, h0, l0);
        split_h2(v.z, v.w, h1, l1);
        ((uint2*)g_bA_hi)[i] = make_uint2(h0, h1);
        ((uint2*)g_bA_lo)[i] = make_uint2(l0, l1);
    } else if (i < PREP_W1) {
        int j = i - PREP_BA;
        float4 v = __ldg(W1 + j);
        split_h2(v.x, v.y, h0, l0);
        split_h2(v.z, v.w, h1, l1);
        ((uint2*)g_w1_hi)[j] = make_uint2(h0, h1);
        ((uint2*)g_w1_lo)[j] = make_uint2(l0, l1);
    } else {
        int j = i - PREP_W1;                 // float4 index into combined W2
        int n = j >> 8, kq = j & 255;        // 256 float4 per 1024-col row
        int blk = n >> 7, r = n & 127;
        const float4* src = (r < 64) ? (W21 + (size_t)(blk * 64 + r) * 256 + kq)
                                     : (W22 + (size_t)(blk * 64 + r - 64) * 256 + kq);
        float4 v = __ldg(src);
        split_h2(v.x, v.y, h0, l0);
        split_h2(v.z, v.w, h1, l1);
        ((uint2*)g_w2_hi)[j] = make_uint2(h0, h1);
        ((uint2*)g_w2_lo)[j] = make_uint2(l0, l1);
    }
}

// ---------------------------------------------------------------------------
// Kernel 1: eps_mean[b,d] = mean_s eps[s,b,d].  419 MB read, HBM-bound.
// ---------------------------------------------------------------------------
__global__ void k_epsmean(const float4* __restrict__ eps4) {
    const int nd4 = Bsz * Dsz / 4;
    int i = blockIdx.x * blockDim.x + threadIdx.x;
    float4 a0 = make_float4(0.f, 0.f, 0.f, 0.f);
    float4 a1 = make_float4(0.f, 0.f, 0.f, 0.f);
#pragma unroll 5
    for (int s = 0; s < Ssz; s += 2) {
        float4 x = eps4[(size_t)s * nd4 + i];
        float4 y = eps4[(size_t)(s + 1) * nd4 + i];
        a0.x += x.x; a0.y += x.y; a0.z += x.z; a0.w += x.w;
        a1.x += y.x; a1.y += y.y; a1.z += y.z; a1.w += y.w;
    }
    const float inv = 1.0f / (float)Ssz;
    float4 r;
    r.x = (a0.x + a1.x) * inv;
    r.y = (a0.y + a1.y) * inv;
    r.z = (a0.z + a1.z) * inv;
    r.w = (a0.w + a1.w) * inv;
    ((float4*)g_epsmean)[i] = r;
}

// ---------------------------------------------------------------------------
// Kernel 2: h = relu(batch @ W1^T + b1).  ldmatrix.x4 fragment loads (4x
// fewer LDS issues), 3-stage cp.async pipeline.  Epilogue writes h in
// split hi/lo form for gemm2.  128x128 CTA tile, BK=32, 256 threads.
// ---------------------------------------------------------------------------
__global__ void __launch_bounds__(256, 1)
k_gemm1(const float* __restrict__ bias) {
    extern __shared__ __align__(16) char sm[];
    const uint32_t sbase = smem_u32(sm);
    const int tid = threadIdx.x, lane = tid & 31, wid = tid >> 5;
    const int warpM = wid >> 2, warpN = wid & 3;
    const int grp = lane >> 2, tig = lane & 3;
    const int rowBase = blockIdx.y * 128, colBase = blockIdx.x * 128;

    // ldmatrix per-lane row offsets (halves), chunk-invariant.
    uint32_t roA[4], roB[2];
#pragma unroll
    for (int mi = 0; mi < 4; mi++)
        roA[mi] = (warpM * 64 + mi * 16 + (lane & 15)) * LDH + ((lane >> 4) * 8);
#pragma unroll
    for (int np = 0; np < 2; np++)
        roB[np] = (warpN * 32 + np * 16 + ((lane >> 4) & 1) * 8 + (lane & 7)) * LDH
                  + (((lane >> 3) & 1) * 8);

    float acc[4][4][4];
#pragma unroll
    for (int mi = 0; mi < 4; mi++)
#pragma unroll
        for (int ni = 0; ni < 4; ni++)
#pragma unroll
            for (int j = 0; j < 4; j++) acc[mi][ni][j] = 0.f;

#define G1_LOAD(c, q)                                                               \
    do {                                                                            \
        int k0 = (c) * 32;                                                          \
        uint32_t sb0 = sbase + (q) * BUF_B;                                         \
        _Pragma("unroll")                                                           \
        for (int it = 0; it < 2; it++) {                                            \
            int f = tid + it * 256;                                                 \
            int r = f >> 2, c8 = f & 3;                                             \
            uint32_t dst = sb0 + (r * LDH + c8 * 8) * 2;                            \
            size_t ao = (size_t)(rowBase + r) * Dsz + k0 + c8 * 8;                  \
            size_t bo = (size_t)(colBase + r) * Dsz + k0 + c8 * 8;                  \
            CP16(dst,              (const char*)g_bA_hi + ao * 2);                  \
            CP16(dst + TILE_B,     (const char*)g_bA_lo + ao * 2);                  \
            CP16(dst + 2 * TILE_B, (const char*)g_w1_hi + bo * 2);                  \
            CP16(dst + 3 * TILE_B, (const char*)g_w1_lo + bo * 2);                  \
        }                                                                           \
        CP_COMMIT();                                                                \
    } while (0)

    G1_LOAD(0, 0);
    G1_LOAD(1, 1);
    for (int c = 0; c < 16; c++) {
        const int q = c % 3;
        if (c + 2 < 16) { G1_LOAD(c + 2, (c + 2) % 3); CP_WAIT2(); }
        else if (c + 1 < 16) { CP_WAIT1(); }
        else { CP_WAIT0(); }
        __syncthreads();
#pragma unroll
        for (int kk = 0; kk < 2; kk++) {
            const uint32_t a_base = sbase + q * BUF_B + kk * 32;
            const uint32_t b_base = a_base + 2 * TILE_B;
            uint32_t ah[4][4], al[4][4], bh[4][2], bl[4][2];
#pragma unroll
            for (int mi = 0; mi < 4; mi++) {
                ldsm4(ah[mi][0], ah[mi][1], ah[mi][2], ah[mi][3], a_base + roA[mi] * 2);
                ldsm4(al[mi][0], al[mi][1], al[mi][2], al[mi][3],
                      a_base + TILE_B + roA[mi] * 2);
            }
#pragma unroll
            for (int np = 0; np < 2; np++) {
                ldsm4(bh[2 * np][0], bh[2 * np][1], bh[2 * np + 1][0], bh[2 * np + 1][1],
                      b_base + roB[np] * 2);
                ldsm4(bl[2 * np][0], bl[2 * np][1], bl[2 * np + 1][0], bl[2 * np + 1][1],
                      b_base + TILE_B + roB[np] * 2);
            }
#pragma unroll
            for (int mi = 0; mi < 4; mi++)
#pragma unroll
                for (int ni = 0; ni < 4; ni++) {
                    mma16(acc[mi][ni], ah[mi], bh[ni]);
                    mma16(acc[mi][ni], ah[mi], bl[ni]);
                    mma16(acc[mi][ni], al[mi], bh[ni]);
                }
        }
        __syncthreads();
    }
#undef G1_LOAD

#pragma unroll
    for (int mi = 0; mi < 4; mi++) {
        int r0 = rowBase + warpM * 64 + mi * 16 + grp;
#pragma unroll
        for (int ni = 0; ni < 4; ni++) {
            int c = colBase + warpN * 32 + ni * 8 + tig * 2;
            float b0 = __ldg(bias + c), b1 = __ldg(bias + c + 1);
            float v00 = fmaxf(acc[mi][ni][0] + b0, 0.f);
            float v01 = fmaxf(acc[mi][ni][1] + b1, 0.f);
            float v10 = fmaxf(acc[mi][ni][2] + b0, 0.f);
            float v11 = fmaxf(acc[mi][ni][3] + b1, 0.f);
            uint32_t h, l;
            split_h2(v00, v01, h, l);
            *(uint32_t*)(g_hA_hi + (size_t)r0 * Hsz + c) = h;
            *(uint32_t*)(g_hA_lo + (size_t)r0 * Hsz + c) = l;
            split_h2(v10, v11, h, l);
            *(uint32_t*)(g_hA_hi + (size_t)(r0 + 8) * Hsz + c) = h;
            *(uint32_t*)(g_hA_lo + (size_t)(r0 + 8) * Hsz + c) = l;
        }
    }
}

// ---------------------------------------------------------------------------
// Kernel 3: fused dual GEMM on pre-split h and combined W2; ldmatrix.x4
// fragment loads, 3-stage cp.async pipeline.  D cols 0-63 = mu, 64-127 =
// log_var.  Epilogue: op = (mu + eps_mean*exp(0.5*lv)) * (batch != 0).
// ---------------------------------------------------------------------------
__global__ void __launch_bounds__(256, 1)
k_gemm2(const float* __restrict__ batch,
        const float* __restrict__ b21, const float* __restrict__ b22) {
    extern __shared__ __align__(16) char sm[];
    const uint32_t sbase = smem_u32(sm);
    const int tid = threadIdx.x, lane = tid & 31, wid = tid >> 5;
    const int warpM = wid >> 2, warpN = wid & 3;
    const int grp = lane >> 2, tig = lane & 3;
    const int rowBase = blockIdx.y * 128, colBase = blockIdx.x * 64;
    const int w2Base = blockIdx.x * 128;   // combined-layout row block

    uint32_t roA[4], roB[2];
#pragma unroll
    for (int mi = 0; mi < 4; mi++)
        roA[mi] = (warpM * 64 + mi * 16 + (lane & 15)) * LDH + ((lane >> 4) * 8);
#pragma unroll
    for (int np = 0; np < 2; np++)
        roB[np] = (warpN * 32 + np * 16 + ((lane >> 4) & 1) * 8 + (lane & 7)) * LDH
                  + (((lane >> 3) & 1) * 8);

    float acc[4][4][4];
#pragma unroll
    for (int mi = 0; mi < 4; mi++)
#pragma unroll
        for (int ni = 0; ni < 4; ni++)
#pragma unroll
            for (int j = 0; j < 4; j++) acc[mi][ni][j] = 0.f;

#define G2_LOAD(c, q)                                                               \
    do {                                                                            \
        int k0 = (c) * 32;                                                          \
        uint32_t sb0 = sbase + (q) * BUF_B;                                         \
        _Pragma("unroll")                                                           \
        for (int it = 0; it < 2; it++) {                                            \
            int f = tid + it * 256;                                                 \
            int r = f >> 2, c8 = f & 3;                                             \
            uint32_t dst = sb0 + (r * LDH + c8 * 8) * 2;                            \
            size_t ao = (size_t)(rowBase + r) * Hsz + k0 + c8 * 8;                  \
            size_t bo = (size_t)(w2Base + r) * Hsz + k0 + c8 * 8;                   \
            CP16(dst,              (const char*)g_hA_hi + ao * 2);                  \
            CP16(dst + TILE_B,     (const char*)g_hA_lo + ao * 2);                  \
            CP16(dst + 2 * TILE_B, (const char*)g_w2_hi + bo * 2);                  \
            CP16(dst + 3 * TILE_B, (const char*)g_w2_lo + bo * 2);                  \
        }                                                                           \
        CP_COMMIT();                                                                \
    } while (0)

    G2_LOAD(0, 0);
    G2_LOAD(1, 1);
    for (int c = 0; c < 32; c++) {
        const int q = c % 3;
        if (c + 2 < 32) { G2_LOAD(c + 2, (c + 2) % 3); CP_WAIT2(); }
        else if (c + 1 < 32) { CP_WAIT1(); }
        else { CP_WAIT0(); }
        __syncthreads();
#pragma unroll
        for (int kk = 0; kk < 2; kk++) {
            const uint32_t a_base = sbase + q * BUF_B + kk * 32;
            const uint32_t b_base = a_base + 2 * TILE_B;
            uint32_t ah[4][4], al[4][4], bh[4][2], bl[4][2];
#pragma unroll
            for (int mi = 0; mi < 4; mi++) {
                ldsm4(ah[mi][0], ah[mi][1], ah[mi][2], ah[mi][3], a_base + roA[mi] * 2);
                ldsm4(al[mi][0], al[mi][1], al[mi][2], al[mi][3],
                      a_base + TILE_B + roA[mi] * 2);
            }
#pragma unroll
            for (int np = 0; np < 2; np++) {
                ldsm4(bh[2 * np][0], bh[2 * np][1], bh[2 * np + 1][0], bh[2 * np + 1][1],
                      b_base + roB[np] * 2);
                ldsm4(bl[2 * np][0], bl[2 * np][1], bl[2 * np + 1][0], bl[2 * np + 1][1],
                      b_base + TILE_B + roB[np] * 2);
            }
#pragma unroll
            for (int mi = 0; mi < 4; mi++)
#pragma unroll
                for (int ni = 0; ni < 4; ni++) {
                    mma16(acc[mi][ni], ah[mi], bh[ni]);
                    mma16(acc[mi][ni], ah[mi], bl[ni]);
                    mma16(acc[mi][ni], al[mi], bh[ni]);
                }
        }
        __syncthreads();
    }
#undef G2_LOAD

    // Stage D (128 x 128) into smem to pair mu (cols 0-63) with lv (64-127).
    float* Dsm = (float*)sm;  // 128*132*4 = 67584 B <= 122880 B
#pragma unroll
    for (int mi = 0; mi < 4; mi++) {
        int r = warpM * 64 + mi * 16 + grp;
#pragma unroll
        for (int ni = 0; ni < 4; ni++) {
            int n = warpN * 32 + ni * 8 + tig * 2;
            *(float2*)&Dsm[r * 132 + n] = make_float2(acc[mi][ni][0], acc[mi][ni][1]);
            *(float2*)&Dsm[(r + 8) * 132 + n] = make_float2(acc[mi][ni][2], acc[mi][ni][3]);
        }
    }
    __syncthreads();

#pragma unroll
    for (int it = 0; it < 8; it++) {
        int f = tid + it * 256;       // 2048 float4 = 128 rows x 16 quad-cols
        int r = f >> 4, c4 = f & 15;
        int gr = rowBase + r, gc = colBase + c4 * 4;
        float4 mu = *(float4*)&Dsm[r * 132 + c4 * 4];
        float4 lv = *(float4*)&Dsm[r * 132 + 64 + c4 * 4];
        float4 bv1 = __ldg((const float4*)(b21 + gc));
        float4 bv2 = __ldg((const float4*)(b22 + gc));
        float4 em = __ldg((const float4*)(g_epsmean + (size_t)gr * Dsz + gc));
        float4 bt = __ldg((const float4*)(batch + (size_t)gr * Dsz + gc));
        float4 o;
        float m0 = mu.x + bv1.x, l0 = lv.x + bv2.x;
        float m1 = mu.y + bv1.y, l1 = lv.y + bv2.y;
        float m2 = mu.z + bv1.z, l2 = lv.z + bv2.z;
        float m3 = mu.w + bv1.w, l3 = lv.w + bv2.w;
        o.x = (bt.x != 0.f) ? (m0 + em.x * __expf(0.5f * l0)) : 0.f;
        o.y = (bt.y != 0.f) ? (m1 + em.y * __expf(0.5f * l1)) : 0.f;
        o.z = (bt.z != 0.f) ? (m2 + em.z * __expf(0.5f * l2)) : 0.f;
        o.w = (bt.w != 0.f) ? (m3 + em.w * __expf(0.5f * l3)) : 0.f;
        *(float4*)(g_op + (size_t)gr * Dsz + gc) = o;
    }
}

// ---------------------------------------------------------------------------
// Kernel 4: stable top-51 of 512 per row.  One warp per TWO rows (ILP),
// radix-select with both counts packed into one __reduce_add_sync.
// ---------------------------------------------------------------------------
__global__ void k_topk(float* __restrict__ out) {
    const int warp = threadIdx.x >> 5;
    const int lane = threadIdx.x & 31;
    const int row0 = blockIdx.x * 16 + warp * 2;

    float v[2][16];
    unsigned u[2][16];
#pragma unroll
    for (int rr = 0; rr < 2; rr++) {
        const float* src = g_op + (size_t)(row0 + rr) * Dsz;
#pragma unroll
        for (int i = 0; i < 16; i++) {
            v[rr][i] = src[lane + 32 * i];
            unsigned b = __float_as_uint(v[rr][i]);
            u[rr][i] = (b & 0x80000000u) ? ~b : (b | 0x80000000u);
        }
    }

    unsigned T0 = 0u, T1 = 0u;
#pragma unroll 1
    for (int bit = 31; bit >= 0; --bit) {
        unsigned cand0 = T0 | (1u << bit);
        unsigned cand1 = T1 | (1u << bit);
        int c0 = 0, c1 = 0;
#pragma unroll
        for (int i = 0; i < 16; i++) {
            c0 += (u[0][i] >= cand0) ? 1 : 0;
            c1 += (u[1][i] >= cand1) ? 1 : 0;
        }
        unsigned s = __reduce_add_sync(0xffffffffu, (unsigned)(c0 | (c1 << 16)));
        if ((s & 0xffffu) >= KTOP) T0 = cand0;
        if ((s >> 16) >= KTOP) T1 = cand1;
    }

    unsigned T[2] = {T0, T1};
#pragma unroll
    for (int rr = 0; rr < 2; rr++) {
        int g = 0;
#pragma unroll
        for (int i = 0; i < 16; i++) g += (u[rr][i] > T[rr]) ? 1 : 0;
        g = (int)__reduce_add_sync(0xffffffffu, (unsigned)g);

        float* dst = out + (size_t)(row0 + rr) * Dsz;
        int pre = g;
#pragma unroll
        for (int i = 0; i < 16; i++) {
            unsigned bal = __ballot_sync(0xffffffffu, u[rr][i] == T[rr]);
            int before = pre + __popc(bal & ((1u << lane) - 1u));
            bool keep = (u[rr][i] > T[rr]) || ((u[rr][i] == T[rr]) && (before < KTOP));
            dst[lane + 32 * i] = keep ? v[rr][i] : 0.f;
            pre += __popc(bal);
        }
    }
}

// ---------------------------------------------------------------------------
extern "C" void kernel_launch(void* const* d_in, const int* in_sizes, int n_in,
                              void* d_out, int out_size) {
    const float* batch = (const float*)d_in[0];
    const float* W1    = (const float*)d_in[1];
    const float* b1    = (const float*)d_in[2];
    const float* W21   = (const float*)d_in[3];
    const float* b21   = (const float*)d_in[4];
    const float* W22   = (const float*)d_in[5];
    const float* b22   = (const float*)d_in[6];
    const float* eps   = (const float*)d_in[7];
    float* out = (float*)d_out;

    cudaFuncSetAttribute(k_gemm1, cudaFuncAttributeMaxDynamicSharedMemorySize, SMEM_TOT);
    cudaFuncSetAttribute(k_gemm2, cudaFuncAttributeMaxDynamicSharedMemorySize, SMEM_TOT);

    // Merged operand prep (batch, W1, combined W2)
    k_prep<<<PREP_TOT / 256, 256>>>((const float4*)batch, (const float4*)W1,
                                    (const float4*)W21, (const float4*)W22);

    k_epsmean<<<(Bsz * Dsz / 4) / 256, 256>>>((const float4*)eps);
    k_gemm1<<<dim3(Hsz / 128, Bsz / 128), 256, SMEM_TOT>>>(b1);
    k_gemm2<<<dim3(Dsz / 64, Bsz / 128), 256, SMEM_TOT>>>(batch, b21, b22);
    k_topk<<<Bsz / 16, 256>>>(out);
}